// round 14
// baseline (speedup 1.0000x reference)
#include <cuda_runtime.h>
#include <cuda_fp16.h>

#define N_NODES 100000
#define N_EDGES 1600000
#define DIM 128
#define EDIM 16
#define NBLK 98             // ceil(100000/1024)

typedef unsigned long long u64;

// f32x2 packed math (sm_103a; ptxas never auto-fuses these)
#define FMA2(d, a, b, c) asm("fma.rn.f32x2 %0, %1, %2, %3;" : "=l"(d) : "l"(a), "l"(b), "l"(c))
#define ADD2(d, a, b)    asm("add.rn.f32x2 %0, %1, %2;"     : "=l"(d) : "l"(a), "l"(b))
#define PACK2(d, lo, hi) asm("mov.b64 %0, {%1, %2};" : "=l"(d) : "r"(__float_as_uint(lo)), "r"(__float_as_uint(hi)))
#define UNPK2(lo, hi, v) do { unsigned _ulo, _uhi; asm("mov.b64 {%0, %1}, %2;" : "=r"(_ulo), "=r"(_uhi) : "l"(v)); lo = __uint_as_float(_ulo); hi = __uint_as_float(_uhi); } while (0)

// ---------------- static scratch (no allocations allowed) ----------------
__device__ __align__(16) float    g_h[N_NODES * DIM];    // node features between layers
__device__ __align__(16) __half   g_glh[N_NODES * DIM];  // x @ Wl + bl (fp16, 25MB)
__device__ __align__(16) float    g_gr[N_NODES * DIM];   // x @ Wr + br
__device__ __align__(16) unsigned g_ea2h[(size_t)N_EDGES * EDIM]; // EA as half2(v,v), 102MB
__device__ int   g_cnt[N_NODES];                      // zero at load; re-zeroed by scan1
__device__ int   g_off[N_NODES + 1];
__device__ int   g_cursor[N_NODES];
__device__ int   g_bsum[128];
__device__ __align__(16) int2 g_einfo[N_EDGES];       // (src, edge_id) sorted by dst
__device__ float g_stats[2 * DIM];                    // sum | sumsq (re-zeroed by bn_finalize)
__device__ float g_bnp[2 * DIM];                      // scale | shift

// ---------------- fused histogram + edge-attr half2 duplication -------------
// edge_index is INT32 (JAX x64-disabled downcast)
__global__ __launch_bounds__(256) void k_histprep(
    const int* __restrict__ ei, int* __restrict__ cnt,
    const float* __restrict__ EA, unsigned* __restrict__ ea2h)
{
    __shared__ float sea[256 * EDIM];
    int e = blockIdx.x * 256 + threadIdx.x;
    atomicAdd(&cnt[ei[N_EDGES + e]], 1);
    size_t base = (size_t)blockIdx.x * 256 * EDIM;
#pragma unroll
    for (int i = 0; i < EDIM; i++) {
        int idx = threadIdx.x + i * 256;
        sea[idx] = EA[base + idx];          // coalesced
    }
    __syncthreads();
#pragma unroll
    for (int i = 0; i < EDIM; i++) {
        int idx = threadIdx.x + i * 256;
        __half2 h = __float2half2_rn(sea[idx]);   // (v, v)
        ea2h[base + idx] = *reinterpret_cast<unsigned*>(&h);  // coalesced
    }
}

__global__ void k_scan1(int* __restrict__ cnt, int* __restrict__ off,
                        int* __restrict__ bsum) {
    __shared__ int s[1024];
    int tid = threadIdx.x;
    int i = blockIdx.x * 1024 + tid;
    int v = (i < N_NODES) ? cnt[i] : 0;
    if (i < N_NODES) cnt[i] = 0;           // re-zero for next call
    s[tid] = v; __syncthreads();
    for (int d = 1; d < 1024; d <<= 1) {
        int t = (tid >= d) ? s[tid - d] : 0;
        __syncthreads();
        s[tid] += t;
        __syncthreads();
    }
    if (i < N_NODES) off[i] = s[tid] - v;   // exclusive within block
    if (tid == 1023) bsum[blockIdx.x] = s[1023];
}

__global__ void k_scan23(int* __restrict__ off, const int* __restrict__ bsum,
                         int* __restrict__ cursor) {
    __shared__ int sp[NBLK];
    int tid = threadIdx.x;
    if (tid == 0) {
        int acc = 0;
        for (int b = 0; b < NBLK; b++) { sp[b] = acc; acc += bsum[b]; }
    }
    __syncthreads();
    int i = blockIdx.x * blockDim.x + tid;
    if (i < N_NODES) {
        int o = off[i] + sp[i >> 10];
        off[i] = o;
        cursor[i] = o;
    }
    if (i == 0) off[N_NODES] = N_EDGES;
}

__global__ void k_scatter(const int* __restrict__ ei, int* __restrict__ cursor,
                          int2* __restrict__ einfo) {
    int e = blockIdx.x * blockDim.x + threadIdx.x;
    if (e < N_EDGES) {
        int src = ei[e];
        int dst = ei[N_EDGES + e];
        int pos = atomicAdd(&cursor[dst], 1);
        einfo[pos] = make_int2(src, e);
    }
}

// ---------------- dual node GEMM: glh = fp16(f(h)@Wl+bl), gr = f(h)@Wr+br ----
#define SXS 20
__global__ __launch_bounds__(128) void k_gemm_dual(
    const float* __restrict__ h, int applyBN, const float* __restrict__ bnp,
    const float* __restrict__ Wl, const float* __restrict__ bl,
    const float* __restrict__ Wr, const float* __restrict__ br,
    __half* __restrict__ glh, float* __restrict__ gr)
{
    __shared__ __align__(16) float sx[128 * SXS];
    __shared__ float sSc[DIM], sSh[DIM];
    int tid = threadIdx.x;
    sSc[tid] = bnp[tid];
    sSh[tid] = bnp[DIM + tid];
    __syncthreads();
    int n0 = blockIdx.x * 16;
    {
        int k = tid;
        float sc = sSc[k], sh = sSh[k];
#pragma unroll
        for (int it = 0; it < 16; it++) {
            float v = h[(size_t)(n0 + it) * DIM + k];
            if (applyBN) {
                v = v * sc + sh;
                v = v > 0.f ? v : 0.02f * v;
            }
            sx[k * SXS + it] = v;
        }
    }
    __syncthreads();
    int j = tid;
    u64 accl[8], accr[8];
    u64 zz; PACK2(zz, 0.f, 0.f);
#pragma unroll
    for (int p = 0; p < 8; p++) { accl[p] = zz; accr[p] = zz; }
#pragma unroll 4
    for (int k = 0; k < 128; k++) {
        float wl = Wl[k * DIM + j];
        float wr = Wr[k * DIM + j];
        u64 wl2, wr2;
        PACK2(wl2, wl, wl);
        PACK2(wr2, wr, wr);
        const ulonglong2* xp2 = (const ulonglong2*)(sx + k * SXS);
#pragma unroll
        for (int p = 0; p < 4; p++) {
            ulonglong2 xv = xp2[p];         // LDS.128
            FMA2(accl[2 * p],     xv.x, wl2, accl[2 * p]);
            FMA2(accr[2 * p],     xv.x, wr2, accr[2 * p]);
            FMA2(accl[2 * p + 1], xv.y, wl2, accl[2 * p + 1]);
            FMA2(accr[2 * p + 1], xv.y, wr2, accr[2 * p + 1]);
        }
    }
    float blv = bl[j], brv = br[j];
#pragma unroll
    for (int p = 0; p < 8; p++) {
        float l0, l1, r0, r1;
        UNPK2(l0, l1, accl[p]);
        UNPK2(r0, r1, accr[p]);
        size_t b0 = (size_t)(n0 + 2 * p) * DIM + j;
        glh[b0] = __float2half_rn(l0 + blv);        gr[b0] = r0 + brv;
        glh[b0 + DIM] = __float2half_rn(l1 + blv);  gr[b0 + DIM] = r1 + brv;
    }
}

// ---------------- final projection (f32x2) ----------------
__global__ __launch_bounds__(128) void k_gemm_final(
    const float* __restrict__ h, const float* __restrict__ bnp,
    const float* __restrict__ Wf, const float* __restrict__ bf,
    float* __restrict__ out)
{
    __shared__ __align__(16) float sx[128 * SXS];
    __shared__ float sSc[DIM], sSh[DIM];
    int tid = threadIdx.x;
    sSc[tid] = bnp[tid];
    sSh[tid] = bnp[DIM + tid];
    __syncthreads();
    int n0 = blockIdx.x * 16;
    {
        int k = tid;
        float sc = sSc[k], sh = sSh[k];
#pragma unroll
        for (int it = 0; it < 16; it++) {
            float v = h[(size_t)(n0 + it) * DIM + k];
            v = v * sc + sh;
            v = v > 0.f ? v : 0.02f * v;
            sx[k * SXS + it] = v;
        }
    }
    __syncthreads();
    int j = tid;
    u64 acc[8];
    u64 zz; PACK2(zz, 0.f, 0.f);
#pragma unroll
    for (int p = 0; p < 8; p++) acc[p] = zz;
#pragma unroll 4
    for (int k = 0; k < 128; k++) {
        float wf = Wf[k * DIM + j];
        u64 wf2; PACK2(wf2, wf, wf);
        const ulonglong2* xp2 = (const ulonglong2*)(sx + k * SXS);
#pragma unroll
        for (int p = 0; p < 4; p++) {
            ulonglong2 xv = xp2[p];
            FMA2(acc[2 * p],     xv.x, wf2, acc[2 * p]);
            FMA2(acc[2 * p + 1], xv.y, wf2, acc[2 * p + 1]);
        }
    }
    float bfv = bf[j];
#pragma unroll
    for (int p = 0; p < 8; p++) {
        float o0, o1;
        UNPK2(o0, o1, acc[p]);
        size_t b0 = (size_t)(n0 + 2 * p) * DIM + j;
        out[b0] = o0 + bfv;
        out[b0 + DIM] = o1 + bfv;
    }
}

// ---------------- fused GATv2 aggregation (transform inlined, fp16) ----------
// One warp per destination node; lane owns channels jb..jb+3 (head = lane>>3).
// Per edge: glh[src] gather (8B/lane) + ea2h[eid] uniform 64B + 32 HFMA2
// transform (identical rounding to the old k_ee) + f32 logit/softmax/accum.
// We as half2 = 32 regs (the fp16 trick that makes fusion viable).
__global__ __launch_bounds__(256) void k_aggregate(
    const int* __restrict__ off, const int2* __restrict__ einfo,
    const unsigned* __restrict__ ea2h,
    const __half* __restrict__ glh, const float* __restrict__ gr,
    const float* __restrict__ We,
    const float* __restrict__ att, const float* __restrict__ bias,
    float* __restrict__ hout, float* __restrict__ stats)
{
    __shared__ float sS[8 * DIM];
    __shared__ float sQ[8 * DIM];
    int tid = threadIdx.x;
    int lane = tid & 31;
    int wrp = tid >> 5;
    int n = blockIdx.x * 8 + wrp;
    int jb = lane * 4;

    __half2 we01h[16], we23h[16];
#pragma unroll
    for (int kk = 0; kk < 16; kk++) {
        float4 wv = *(const float4*)(We + kk * DIM + jb);
        we01h[kk] = __floats2half2_rn(wv.x, wv.y);
        we23h[kk] = __floats2half2_rn(wv.z, wv.w);
    }
    float4 a4 = *(const float4*)(att + jb);
    float4 b4 = *(const float4*)(bias + jb);

    float o0 = 0.f, o1 = 0.f, o2 = 0.f, o3 = 0.f;
    if (n < N_NODES) {
        ulonglong2 grv = *(const ulonglong2*)(gr + (size_t)n * DIM + jb);
        u64 gr01 = grv.x, gr23 = grv.y;
        u64 acc01, acc23;
        PACK2(acc01, 0.f, 0.f);
        acc23 = acc01;
        float den = 0.f;
        int beg = off[n], end = off[n + 1];
#pragma unroll 2
        for (int p = beg; p < end; p++) {
            int2 se = einfo[p];
            uint2 gv = *(const uint2*)(glh + (size_t)se.x * DIM + jb);  // 8B gather
            const uint4* ep = (const uint4*)(ea2h + (size_t)se.y * EDIM);
            uint4 ua = ep[0], ub = ep[1], uc = ep[2], ud = ep[3];       // uniform 64B
            // fp16 edge transform (same math/rounding as old k_ee)
            __half2 z = __float2half2_rn(0.f);
            __half2 a01 = z, b01 = z, a23 = z, b23 = z;
#define EE_STEP(u, k0)                                                        \
            {                                                                 \
                __half2 s0 = *reinterpret_cast<__half2*>(&(u).x);             \
                __half2 s1 = *reinterpret_cast<__half2*>(&(u).y);             \
                __half2 s2 = *reinterpret_cast<__half2*>(&(u).z);             \
                __half2 s3 = *reinterpret_cast<__half2*>(&(u).w);             \
                a01 = __hfma2(s0, we01h[(k0) + 0], a01);                      \
                a23 = __hfma2(s0, we23h[(k0) + 0], a23);                      \
                b01 = __hfma2(s1, we01h[(k0) + 1], b01);                      \
                b23 = __hfma2(s1, we23h[(k0) + 1], b23);                      \
                a01 = __hfma2(s2, we01h[(k0) + 2], a01);                      \
                a23 = __hfma2(s2, we23h[(k0) + 2], a23);                      \
                b01 = __hfma2(s3, we01h[(k0) + 3], b01);                      \
                b23 = __hfma2(s3, we23h[(k0) + 3], b23);                      \
            }
            EE_STEP(ua, 0)
            EE_STEP(ub, 4)
            EE_STEP(uc, 8)
            EE_STEP(ud, 12)
#undef EE_STEP
            __half2 r01 = __hadd2(a01, b01);
            __half2 r23 = __hadd2(a23, b23);
            // to f32 and combine with gl + gr
            __half2 ga = *reinterpret_cast<__half2*>(&gv.x);
            __half2 gb = *reinterpret_cast<__half2*>(&gv.y);
            float2 gf0 = __half22float2(ga);
            float2 gf1 = __half22float2(gb);
            float2 ef0 = __half22float2(r01);
            float2 ef1 = __half22float2(r23);
            u64 g01, g23, ee01, ee23;
            PACK2(g01, gf0.x, gf0.y);
            PACK2(g23, gf1.x, gf1.y);
            PACK2(ee01, ef0.x, ef0.y);
            PACK2(ee23, ef1.x, ef1.y);
            u64 e01, e23;
            ADD2(e01, g01, gr01);
            ADD2(e23, g23, gr23);
            ADD2(e01, e01, ee01);
            ADD2(e23, e23, ee23);
            float x0, x1, x2, x3;
            UNPK2(x0, x1, e01);
            UNPK2(x2, x3, e23);
            x0 = x0 > 0.f ? x0 : 0.2f * x0;     // GATv2 leaky relu 0.2
            x1 = x1 > 0.f ? x1 : 0.2f * x1;
            x2 = x2 > 0.f ? x2 : 0.2f * x2;
            x3 = x3 > 0.f ? x3 : 0.2f * x3;
            float t = x0 * a4.x;
            t = fmaf(x1, a4.y, t);
            t = fmaf(x2, a4.z, t);
            t = fmaf(x3, a4.w, t);
            t += __shfl_xor_sync(0xffffffffu, t, 1);
            t += __shfl_xor_sync(0xffffffffu, t, 2);
            t += __shfl_xor_sync(0xffffffffu, t, 4);
            float w = __expf(t);
            den += w;
            u64 ww; PACK2(ww, w, w);
            FMA2(acc01, ww, g01, acc01);
            FMA2(acc23, ww, g23, acc23);
        }
        float rden = 1.0f / (den + 1e-16f);
        float a0, a1, a2, a3;
        UNPK2(a0, a1, acc01);
        UNPK2(a2, a3, acc23);
        o0 = a0 * rden + b4.x;
        o1 = a1 * rden + b4.y;
        o2 = a2 * rden + b4.z;
        o3 = a3 * rden + b4.w;
        *(float4*)(hout + (size_t)n * DIM + jb) = make_float4(o0, o1, o2, o3);
    }
    // BN partials: per-warp disjoint smem slices, no smem atomics
    int base = wrp * DIM + jb;
    sS[base + 0] = o0;  sQ[base + 0] = o0 * o0;
    sS[base + 1] = o1;  sQ[base + 1] = o1 * o1;
    sS[base + 2] = o2;  sQ[base + 2] = o2 * o2;
    sS[base + 3] = o3;  sQ[base + 3] = o3 * o3;
    __syncthreads();
    if (tid < DIM) {
        float s = 0.f, q = 0.f;
#pragma unroll
        for (int w = 0; w < 8; w++) {
            s += sS[w * DIM + tid];
            q += sQ[w * DIM + tid];
        }
        atomicAdd(&stats[tid], s);
        atomicAdd(&stats[DIM + tid], q);
    }
}

// ---------------- BN stats finalize (and reset accumulators) ----------------
__global__ void k_bn_finalize(float* __restrict__ stats,
                              const float* __restrict__ gamma,
                              const float* __restrict__ beta,
                              float* __restrict__ bnp)
{
    int j = threadIdx.x;
    float inv_n = 1.0f / (float)N_NODES;
    float mu = stats[j] * inv_n;
    float var = stats[DIM + j] * inv_n - mu * mu;
    float rs = rsqrtf(var + 1e-5f);
    float sc = rs * gamma[j];
    bnp[j] = sc;
    bnp[DIM + j] = beta[j] - mu * sc;
    stats[j] = 0.f;
    stats[DIM + j] = 0.f;
}

// ---------------- launch ----------------
extern "C" void kernel_launch(void* const* d_in, const int* in_sizes, int n_in,
                              void* d_out, int out_size)
{
    const float* x    = (const float*)d_in[0];
    const int*   ei   = (const int*)d_in[1];     // int32
    const float* ea   = (const float*)d_in[2];
    const float* Wl   = (const float*)d_in[3];
    const float* bl   = (const float*)d_in[4];
    const float* Wr   = (const float*)d_in[5];
    const float* br   = (const float*)d_in[6];
    const float* We   = (const float*)d_in[7];
    const float* att  = (const float*)d_in[8];
    const float* bias = (const float*)d_in[9];
    const float* gamma= (const float*)d_in[10];
    const float* beta = (const float*)d_in[11];
    const float* Wf   = (const float*)d_in[12];
    const float* bf   = (const float*)d_in[13];
    float* out = (float*)d_out;

    float *p_h, *p_gr, *p_stats, *p_bnp;
    unsigned *p_ea2h;
    __half *p_glh;
    int *p_cnt, *p_off, *p_cur, *p_bsum;
    int2 *p_einfo;
    cudaGetSymbolAddress((void**)&p_h,     g_h);
    cudaGetSymbolAddress((void**)&p_glh,   g_glh);
    cudaGetSymbolAddress((void**)&p_gr,    g_gr);
    cudaGetSymbolAddress((void**)&p_ea2h,  g_ea2h);
    cudaGetSymbolAddress((void**)&p_stats, g_stats);
    cudaGetSymbolAddress((void**)&p_bnp,   g_bnp);
    cudaGetSymbolAddress((void**)&p_cnt,   g_cnt);
    cudaGetSymbolAddress((void**)&p_off,   g_off);
    cudaGetSymbolAddress((void**)&p_cur,   g_cursor);
    cudaGetSymbolAddress((void**)&p_bsum,  g_bsum);
    cudaGetSymbolAddress((void**)&p_einfo, g_einfo);

    int gemm_blocks = N_NODES / 16;            // 6250 (exact)
    int agg_blocks  = N_NODES / 8;             // 12500 (exact)

    // launch #4 = k_gemm_dual (ncu capture slot)
    k_histprep<<<N_EDGES / 256, 256>>>(ei, p_cnt, ea, p_ea2h);           // 1
    k_scan1<<<NBLK, 1024>>>(p_cnt, p_off, p_bsum);                       // 2
    k_scan23<<<(N_NODES + 255) / 256, 256>>>(p_off, p_bsum, p_cur);      // 3
    k_gemm_dual<<<gemm_blocks, 128>>>(x, 0, p_bnp, Wl, bl, Wr, br,
                                      p_glh, p_gr);                      // 4 (profiled)
    k_scatter<<<(N_EDGES + 255) / 256, 256>>>(ei, p_cur, p_einfo);       // 5

    for (int L = 0; L < 3; L++) {
        if (L > 0) {
            k_gemm_dual<<<gemm_blocks, 128>>>(p_h, 1, p_bnp,
                                              Wl + L * DIM * DIM, bl + L * DIM,
                                              Wr + L * DIM * DIM, br + L * DIM,
                                              p_glh, p_gr);
        }
        k_aggregate<<<agg_blocks, 256>>>(p_off, p_einfo, p_ea2h, p_glh, p_gr,
                                         We + L * EDIM * DIM,
                                         att + L * DIM, bias + L * DIM,
                                         p_h, p_stats);
        k_bn_finalize<<<1, 128>>>(p_stats, gamma + L * DIM, beta + L * DIM, p_bnp);
    }
    k_gemm_final<<<gemm_blocks, 128>>>(p_h, p_bnp, Wf, bf, out);
}

// round 15
// speedup vs baseline: 1.3462x; 1.3462x over previous
#include <cuda_runtime.h>
#include <cuda_fp16.h>

#define N_NODES 100000
#define N_EDGES 1600000
#define DIM 128
#define EDIM 16
#define NBLK 98             // ceil(100000/1024)

typedef unsigned long long u64;

// f32x2 packed math (sm_103a; ptxas never auto-fuses these)
#define FMA2(d, a, b, c) asm("fma.rn.f32x2 %0, %1, %2, %3;" : "=l"(d) : "l"(a), "l"(b), "l"(c))
#define ADD2(d, a, b)    asm("add.rn.f32x2 %0, %1, %2;"     : "=l"(d) : "l"(a), "l"(b))
#define PACK2(d, lo, hi) asm("mov.b64 %0, {%1, %2};" : "=l"(d) : "r"(__float_as_uint(lo)), "r"(__float_as_uint(hi)))
#define UNPK2(lo, hi, v) do { unsigned _ulo, _uhi; asm("mov.b64 {%0, %1}, %2;" : "=r"(_ulo), "=r"(_uhi) : "l"(v)); lo = __uint_as_float(_ulo); hi = __uint_as_float(_uhi); } while (0)

// ---------------- static scratch (no allocations allowed) ----------------
__device__ __align__(16) float    g_h[N_NODES * DIM];    // node features between layers
__device__ __align__(16) __half   g_glh[N_NODES * DIM];  // x @ Wl + bl (fp16, 25MB)
__device__ __align__(16) float    g_gr[N_NODES * DIM];   // x @ Wr + br
__device__ __align__(16) unsigned g_ea2h[(size_t)N_EDGES * EDIM]; // EA as half2(v,v)
__device__ __align__(16) __half   g_ee[(size_t)N_EDGES * DIM];    // EA @ We, fp16 (410MB)
__device__ int   g_cnt[N_NODES];                      // zero at load; re-zeroed by scan1
__device__ int   g_off[N_NODES + 1];
__device__ int   g_cursor[N_NODES];
__device__ int   g_bsum[128];
__device__ __align__(16) int2 g_einfo[N_EDGES];       // (src, edge_id) sorted by dst
__device__ float g_stats[2 * DIM];                    // sum | sumsq (re-zeroed by bn_finalize)
__device__ float g_bnp[2 * DIM];                      // scale | shift

// ---------------- fused histogram + edge-attr half2 duplication -------------
// edge_index is INT32 (JAX x64-disabled downcast)
__global__ __launch_bounds__(256) void k_histprep(
    const int* __restrict__ ei, int* __restrict__ cnt,
    const float* __restrict__ EA, unsigned* __restrict__ ea2h)
{
    __shared__ float sea[256 * EDIM];
    int e = blockIdx.x * 256 + threadIdx.x;
    atomicAdd(&cnt[ei[N_EDGES + e]], 1);
    size_t base = (size_t)blockIdx.x * 256 * EDIM;
#pragma unroll
    for (int i = 0; i < EDIM; i++) {
        int idx = threadIdx.x + i * 256;
        sea[idx] = EA[base + idx];          // coalesced
    }
    __syncthreads();
#pragma unroll
    for (int i = 0; i < EDIM; i++) {
        int idx = threadIdx.x + i * 256;
        __half2 h = __float2half2_rn(sea[idx]);   // (v, v)
        ea2h[base + idx] = *reinterpret_cast<unsigned*>(&h);  // coalesced
    }
}

__global__ void k_scan1(int* __restrict__ cnt, int* __restrict__ off,
                        int* __restrict__ bsum) {
    __shared__ int s[1024];
    int tid = threadIdx.x;
    int i = blockIdx.x * 1024 + tid;
    int v = (i < N_NODES) ? cnt[i] : 0;
    if (i < N_NODES) cnt[i] = 0;           // re-zero for next call
    s[tid] = v; __syncthreads();
    for (int d = 1; d < 1024; d <<= 1) {
        int t = (tid >= d) ? s[tid - d] : 0;
        __syncthreads();
        s[tid] += t;
        __syncthreads();
    }
    if (i < N_NODES) off[i] = s[tid] - v;   // exclusive within block
    if (tid == 1023) bsum[blockIdx.x] = s[1023];
}

__global__ void k_scan23(int* __restrict__ off, const int* __restrict__ bsum,
                         int* __restrict__ cursor) {
    __shared__ int sp[NBLK];
    int tid = threadIdx.x;
    if (tid == 0) {
        int acc = 0;
        for (int b = 0; b < NBLK; b++) { sp[b] = acc; acc += bsum[b]; }
    }
    __syncthreads();
    int i = blockIdx.x * blockDim.x + tid;
    if (i < N_NODES) {
        int o = off[i] + sp[i >> 10];
        off[i] = o;
        cursor[i] = o;
    }
    if (i == 0) off[N_NODES] = N_EDGES;
}

__global__ void k_scatter(const int* __restrict__ ei, int* __restrict__ cursor,
                          int2* __restrict__ einfo) {
    int e = blockIdx.x * blockDim.x + threadIdx.x;
    if (e < N_EDGES) {
        int src = ei[e];
        int dst = ei[N_EDGES + e];
        int pos = atomicAdd(&cursor[dst], 1);
        einfo[pos] = make_int2(src, e);
    }
}

// ---------------- dual node GEMM: glh = fp16(f(h)@Wl+bl), gr = f(h)@Wr+br ----
#define SXS 20
__global__ __launch_bounds__(128) void k_gemm_dual(
    const float* __restrict__ h, int applyBN, const float* __restrict__ bnp,
    const float* __restrict__ Wl, const float* __restrict__ bl,
    const float* __restrict__ Wr, const float* __restrict__ br,
    __half* __restrict__ glh, float* __restrict__ gr)
{
    __shared__ __align__(16) float sx[128 * SXS];
    __shared__ float sSc[DIM], sSh[DIM];
    int tid = threadIdx.x;
    sSc[tid] = bnp[tid];
    sSh[tid] = bnp[DIM + tid];
    __syncthreads();
    int n0 = blockIdx.x * 16;
    {
        int k = tid;
        float sc = sSc[k], sh = sSh[k];
#pragma unroll
        for (int it = 0; it < 16; it++) {
            float v = h[(size_t)(n0 + it) * DIM + k];
            if (applyBN) {
                v = v * sc + sh;
                v = v > 0.f ? v : 0.02f * v;
            }
            sx[k * SXS + it] = v;
        }
    }
    __syncthreads();
    int j = tid;
    u64 accl[8], accr[8];
    u64 zz; PACK2(zz, 0.f, 0.f);
#pragma unroll
    for (int p = 0; p < 8; p++) { accl[p] = zz; accr[p] = zz; }
#pragma unroll 4
    for (int k = 0; k < 128; k++) {
        float wl = Wl[k * DIM + j];
        float wr = Wr[k * DIM + j];
        u64 wl2, wr2;
        PACK2(wl2, wl, wl);
        PACK2(wr2, wr, wr);
        const ulonglong2* xp2 = (const ulonglong2*)(sx + k * SXS);
#pragma unroll
        for (int p = 0; p < 4; p++) {
            ulonglong2 xv = xp2[p];         // LDS.128
            FMA2(accl[2 * p],     xv.x, wl2, accl[2 * p]);
            FMA2(accr[2 * p],     xv.x, wr2, accr[2 * p]);
            FMA2(accl[2 * p + 1], xv.y, wl2, accl[2 * p + 1]);
            FMA2(accr[2 * p + 1], xv.y, wr2, accr[2 * p + 1]);
        }
    }
    float blv = bl[j], brv = br[j];
#pragma unroll
    for (int p = 0; p < 8; p++) {
        float l0, l1, r0, r1;
        UNPK2(l0, l1, accl[p]);
        UNPK2(r0, r1, accr[p]);
        size_t b0 = (size_t)(n0 + 2 * p) * DIM + j;
        glh[b0] = __float2half_rn(l0 + blv);        gr[b0] = r0 + brv;
        glh[b0 + DIM] = __float2half_rn(l1 + blv);  gr[b0 + DIM] = r1 + brv;
    }
}

// ---------------- final projection (f32x2) ----------------
__global__ __launch_bounds__(128) void k_gemm_final(
    const float* __restrict__ h, const float* __restrict__ bnp,
    const float* __restrict__ Wf, const float* __restrict__ bf,
    float* __restrict__ out)
{
    __shared__ __align__(16) float sx[128 * SXS];
    __shared__ float sSc[DIM], sSh[DIM];
    int tid = threadIdx.x;
    sSc[tid] = bnp[tid];
    sSh[tid] = bnp[DIM + tid];
    __syncthreads();
    int n0 = blockIdx.x * 16;
    {
        int k = tid;
        float sc = sSc[k], sh = sSh[k];
#pragma unroll
        for (int it = 0; it < 16; it++) {
            float v = h[(size_t)(n0 + it) * DIM + k];
            v = v * sc + sh;
            v = v > 0.f ? v : 0.02f * v;
            sx[k * SXS + it] = v;
        }
    }
    __syncthreads();
    int j = tid;
    u64 acc[8];
    u64 zz; PACK2(zz, 0.f, 0.f);
#pragma unroll
    for (int p = 0; p < 8; p++) acc[p] = zz;
#pragma unroll 4
    for (int k = 0; k < 128; k++) {
        float wf = Wf[k * DIM + j];
        u64 wf2; PACK2(wf2, wf, wf);
        const ulonglong2* xp2 = (const ulonglong2*)(sx + k * SXS);
#pragma unroll
        for (int p = 0; p < 4; p++) {
            ulonglong2 xv = xp2[p];
            FMA2(acc[2 * p],     xv.x, wf2, acc[2 * p]);
            FMA2(acc[2 * p + 1], xv.y, wf2, acc[2 * p + 1]);
        }
    }
    float bfv = bf[j];
#pragma unroll
    for (int p = 0; p < 8; p++) {
        float o0, o1;
        UNPK2(o0, o1, acc[p]);
        size_t b0 = (size_t)(n0 + 2 * p) * DIM + j;
        out[b0] = o0 + bfv;
        out[b0 + DIM] = o1 + bfv;
    }
}

// ---------------- edge transform GEMM: ee[e] = EA[e] @ We (all-fp16) ---------
// smem-staged (R13-measured: 109us, fma 80%, DRAM 52%).
__global__ __launch_bounds__(256) void k_ee(
    const unsigned* __restrict__ ea2h, const float* __restrict__ We,
    __half* __restrict__ ee)
{
    __shared__ __align__(16) uint4 sbuf[256 * 4];   // 256 edges x 64B = 16KB
    int tid = threadIdx.x;
    int lane = tid & 31;
    int wrp = tid >> 5;
    int jb = lane * 4;

    __half2 we01h[16], we23h[16];
#pragma unroll
    for (int kk = 0; kk < 16; kk++) {
        float4 wv = *(const float4*)(We + kk * DIM + jb);
        we01h[kk] = __floats2half2_rn(wv.x, wv.y);
        we23h[kk] = __floats2half2_rn(wv.z, wv.w);
    }

    size_t ebase = (size_t)blockIdx.x * 256;
    const uint4* gp = (const uint4*)(ea2h + ebase * EDIM);
#pragma unroll
    for (int i = 0; i < 4; i++)
        sbuf[tid + i * 256] = gp[tid + i * 256];    // coalesced, MLP=4/thread
    __syncthreads();

    int le0 = wrp * 32;
#pragma unroll 2
    for (int q = 0; q < 32; q++) {
        int le = le0 + q;
        uint4 ua = sbuf[le * 4 + 0];                // LDS.128 broadcast
        uint4 ub = sbuf[le * 4 + 1];
        uint4 uc = sbuf[le * 4 + 2];
        uint4 ud = sbuf[le * 4 + 3];
        __half2 z = __float2half2_rn(0.f);
        __half2 a01 = z, b01 = z, a23 = z, b23 = z;
#define EE_STEP(u, k0)                                                        \
        {                                                                     \
            __half2 s0 = *reinterpret_cast<__half2*>(&(u).x);                 \
            __half2 s1 = *reinterpret_cast<__half2*>(&(u).y);                 \
            __half2 s2 = *reinterpret_cast<__half2*>(&(u).z);                 \
            __half2 s3 = *reinterpret_cast<__half2*>(&(u).w);                 \
            a01 = __hfma2(s0, we01h[(k0) + 0], a01);                          \
            a23 = __hfma2(s0, we23h[(k0) + 0], a23);                          \
            b01 = __hfma2(s1, we01h[(k0) + 1], b01);                          \
            b23 = __hfma2(s1, we23h[(k0) + 1], b23);                          \
            a01 = __hfma2(s2, we01h[(k0) + 2], a01);                          \
            a23 = __hfma2(s2, we23h[(k0) + 2], a23);                          \
            b01 = __hfma2(s3, we01h[(k0) + 3], b01);                          \
            b23 = __hfma2(s3, we23h[(k0) + 3], b23);                          \
        }
        EE_STEP(ua, 0)
        EE_STEP(ub, 4)
        EE_STEP(uc, 8)
        EE_STEP(ud, 12)
#undef EE_STEP
        __half2 r01 = __hadd2(a01, b01);
        __half2 r23 = __hadd2(a23, b23);
        uint2 o;
        o.x = *reinterpret_cast<unsigned*>(&r01);
        o.y = *reinterpret_cast<unsigned*>(&r23);
        *(uint2*)(ee + (ebase + le) * DIM + jb) = o;   // 256B coalesced per warp
    }
}

// ---------------- fused GATv2 aggregation: one warp per destination node -----
// 4-edge batched gathers: 8 independent loads issued before compute -> MLP ~4.
__device__ __forceinline__ void agg_edge(
    uint2 ev, uint2 gv, u64 gr01, u64 gr23, float4 a4,
    u64& acc01, u64& acc23, float& den)
{
    __half2 ha = *reinterpret_cast<__half2*>(&ev.x);
    __half2 hb = *reinterpret_cast<__half2*>(&ev.y);
    __half2 ga = *reinterpret_cast<__half2*>(&gv.x);
    __half2 gb = *reinterpret_cast<__half2*>(&gv.y);
    float2 ef0 = __half22float2(ha);
    float2 ef1 = __half22float2(hb);
    float2 gf0 = __half22float2(ga);
    float2 gf1 = __half22float2(gb);
    u64 ee01, ee23, g01, g23;
    PACK2(ee01, ef0.x, ef0.y);
    PACK2(ee23, ef1.x, ef1.y);
    PACK2(g01, gf0.x, gf0.y);
    PACK2(g23, gf1.x, gf1.y);
    u64 e01, e23;
    ADD2(e01, g01, gr01);
    ADD2(e23, g23, gr23);
    ADD2(e01, e01, ee01);
    ADD2(e23, e23, ee23);
    float x0, x1, x2, x3;
    UNPK2(x0, x1, e01);
    UNPK2(x2, x3, e23);
    x0 = x0 > 0.f ? x0 : 0.2f * x0;     // GATv2 leaky relu 0.2
    x1 = x1 > 0.f ? x1 : 0.2f * x1;
    x2 = x2 > 0.f ? x2 : 0.2f * x2;
    x3 = x3 > 0.f ? x3 : 0.2f * x3;
    float t = x0 * a4.x;
    t = fmaf(x1, a4.y, t);
    t = fmaf(x2, a4.z, t);
    t = fmaf(x3, a4.w, t);
    t += __shfl_xor_sync(0xffffffffu, t, 1);
    t += __shfl_xor_sync(0xffffffffu, t, 2);
    t += __shfl_xor_sync(0xffffffffu, t, 4);
    float w = __expf(t);
    den += w;
    u64 ww; PACK2(ww, w, w);
    FMA2(acc01, ww, g01, acc01);
    FMA2(acc23, ww, g23, acc23);
}

__global__ __launch_bounds__(256) void k_aggregate(
    const int* __restrict__ off, const int2* __restrict__ einfo,
    const __half* __restrict__ ee,
    const __half* __restrict__ glh, const float* __restrict__ gr,
    const float* __restrict__ att, const float* __restrict__ bias,
    float* __restrict__ hout, float* __restrict__ stats)
{
    __shared__ float sS[8 * DIM];
    __shared__ float sQ[8 * DIM];
    int tid = threadIdx.x;
    int lane = tid & 31;
    int wrp = tid >> 5;
    int n = blockIdx.x * 8 + wrp;
    int jb = lane * 4;

    float4 a4 = *(const float4*)(att + jb);
    float4 b4 = *(const float4*)(bias + jb);

    float o0 = 0.f, o1 = 0.f, o2 = 0.f, o3 = 0.f;
    if (n < N_NODES) {
        ulonglong2 grv = *(const ulonglong2*)(gr + (size_t)n * DIM + jb);
        u64 gr01 = grv.x, gr23 = grv.y;
        u64 acc01, acc23;
        PACK2(acc01, 0.f, 0.f);
        acc23 = acc01;
        float den = 0.f;
        int beg = off[n], end = off[n + 1];
        int p = beg;
        // 4-edge batches: issue all 8 gathers, then compute 4 independent bodies
#pragma unroll 1
        for (; p + 3 < end; p += 4) {
            int2 s0 = einfo[p + 0];
            int2 s1 = einfo[p + 1];
            int2 s2 = einfo[p + 2];
            int2 s3 = einfo[p + 3];
            uint2 ev0 = *(const uint2*)(ee + (size_t)s0.y * DIM + jb);
            uint2 ev1 = *(const uint2*)(ee + (size_t)s1.y * DIM + jb);
            uint2 ev2 = *(const uint2*)(ee + (size_t)s2.y * DIM + jb);
            uint2 ev3 = *(const uint2*)(ee + (size_t)s3.y * DIM + jb);
            uint2 gv0 = *(const uint2*)(glh + (size_t)s0.x * DIM + jb);
            uint2 gv1 = *(const uint2*)(glh + (size_t)s1.x * DIM + jb);
            uint2 gv2 = *(const uint2*)(glh + (size_t)s2.x * DIM + jb);
            uint2 gv3 = *(const uint2*)(glh + (size_t)s3.x * DIM + jb);
            agg_edge(ev0, gv0, gr01, gr23, a4, acc01, acc23, den);
            agg_edge(ev1, gv1, gr01, gr23, a4, acc01, acc23, den);
            agg_edge(ev2, gv2, gr01, gr23, a4, acc01, acc23, den);
            agg_edge(ev3, gv3, gr01, gr23, a4, acc01, acc23, den);
        }
        for (; p < end; p++) {
            int2 se = einfo[p];
            uint2 ev = *(const uint2*)(ee + (size_t)se.y * DIM + jb);
            uint2 gv = *(const uint2*)(glh + (size_t)se.x * DIM + jb);
            agg_edge(ev, gv, gr01, gr23, a4, acc01, acc23, den);
        }
        float rden = 1.0f / (den + 1e-16f);
        float a0, a1, a2, a3;
        UNPK2(a0, a1, acc01);
        UNPK2(a2, a3, acc23);
        o0 = a0 * rden + b4.x;
        o1 = a1 * rden + b4.y;
        o2 = a2 * rden + b4.z;
        o3 = a3 * rden + b4.w;
        *(float4*)(hout + (size_t)n * DIM + jb) = make_float4(o0, o1, o2, o3);
    }
    // BN partials: per-warp disjoint smem slices, no smem atomics
    int base = wrp * DIM + jb;
    sS[base + 0] = o0;  sQ[base + 0] = o0 * o0;
    sS[base + 1] = o1;  sQ[base + 1] = o1 * o1;
    sS[base + 2] = o2;  sQ[base + 2] = o2 * o2;
    sS[base + 3] = o3;  sQ[base + 3] = o3 * o3;
    __syncthreads();
    if (tid < DIM) {
        float s = 0.f, q = 0.f;
#pragma unroll
        for (int w = 0; w < 8; w++) {
            s += sS[w * DIM + tid];
            q += sQ[w * DIM + tid];
        }
        atomicAdd(&stats[tid], s);
        atomicAdd(&stats[DIM + tid], q);
    }
}

// ---------------- BN stats finalize (and reset accumulators) ----------------
__global__ void k_bn_finalize(float* __restrict__ stats,
                              const float* __restrict__ gamma,
                              const float* __restrict__ beta,
                              float* __restrict__ bnp)
{
    int j = threadIdx.x;
    float inv_n = 1.0f / (float)N_NODES;
    float mu = stats[j] * inv_n;
    float var = stats[DIM + j] * inv_n - mu * mu;
    float rs = rsqrtf(var + 1e-5f);
    float sc = rs * gamma[j];
    bnp[j] = sc;
    bnp[DIM + j] = beta[j] - mu * sc;
    stats[j] = 0.f;
    stats[DIM + j] = 0.f;
}

// ---------------- launch ----------------
extern "C" void kernel_launch(void* const* d_in, const int* in_sizes, int n_in,
                              void* d_out, int out_size)
{
    const float* x    = (const float*)d_in[0];
    const int*   ei   = (const int*)d_in[1];     // int32
    const float* ea   = (const float*)d_in[2];
    const float* Wl   = (const float*)d_in[3];
    const float* bl   = (const float*)d_in[4];
    const float* Wr   = (const float*)d_in[5];
    const float* br   = (const float*)d_in[6];
    const float* We   = (const float*)d_in[7];
    const float* att  = (const float*)d_in[8];
    const float* bias = (const float*)d_in[9];
    const float* gamma= (const float*)d_in[10];
    const float* beta = (const float*)d_in[11];
    const float* Wf   = (const float*)d_in[12];
    const float* bf   = (const float*)d_in[13];
    float* out = (float*)d_out;

    float *p_h, *p_gr, *p_stats, *p_bnp;
    unsigned *p_ea2h;
    __half *p_ee, *p_glh;
    int *p_cnt, *p_off, *p_cur, *p_bsum;
    int2 *p_einfo;
    cudaGetSymbolAddress((void**)&p_h,     g_h);
    cudaGetSymbolAddress((void**)&p_glh,   g_glh);
    cudaGetSymbolAddress((void**)&p_gr,    g_gr);
    cudaGetSymbolAddress((void**)&p_ea2h,  g_ea2h);
    cudaGetSymbolAddress((void**)&p_ee,    g_ee);
    cudaGetSymbolAddress((void**)&p_stats, g_stats);
    cudaGetSymbolAddress((void**)&p_bnp,   g_bnp);
    cudaGetSymbolAddress((void**)&p_cnt,   g_cnt);
    cudaGetSymbolAddress((void**)&p_off,   g_off);
    cudaGetSymbolAddress((void**)&p_cur,   g_cursor);
    cudaGetSymbolAddress((void**)&p_bsum,  g_bsum);
    cudaGetSymbolAddress((void**)&p_einfo, g_einfo);

    int gemm_blocks = N_NODES / 16;            // 6250 (exact)
    int agg_blocks  = N_NODES / 8;             // 12500 (exact)
    int ee_blocks   = N_EDGES / 256;           // 6250

    // launch #4 = k_ee (ncu capture slot); k_ee depends only on histprep.
    k_histprep<<<N_EDGES / 256, 256>>>(ei, p_cnt, ea, p_ea2h);           // 1
    k_gemm_dual<<<gemm_blocks, 128>>>(x, 0, p_bnp, Wl, bl, Wr, br,
                                      p_glh, p_gr);                      // 2
    k_scan1<<<NBLK, 1024>>>(p_cnt, p_off, p_bsum);                       // 3
    k_ee<<<ee_blocks, 256>>>(p_ea2h, We, p_ee);                          // 4 (profiled)
    k_scan23<<<(N_NODES + 255) / 256, 256>>>(p_off, p_bsum, p_cur);      // 5
    k_scatter<<<(N_EDGES + 255) / 256, 256>>>(ei, p_cur, p_einfo);       // 6

    for (int L = 0; L < 3; L++) {
        if (L > 0) {
            k_gemm_dual<<<gemm_blocks, 128>>>(p_h, 1, p_bnp,
                                              Wl + L * DIM * DIM, bl + L * DIM,
                                              Wr + L * DIM * DIM, br + L * DIM,
                                              p_glh, p_gr);
            k_ee<<<ee_blocks, 256>>>(p_ea2h, We + L * EDIM * DIM, p_ee);
        }
        k_aggregate<<<agg_blocks, 256>>>(p_off, p_einfo, p_ee, p_glh, p_gr,
                                         att + L * DIM, bias + L * DIM,
                                         p_h, p_stats);
        k_bn_finalize<<<1, 128>>>(p_stats, gamma + L * DIM, beta + L * DIM, p_bnp);
    }
    k_gemm_final<<<gemm_blocks, 128>>>(p_h, p_bnp, Wf, bf, out);
}

// round 16
// speedup vs baseline: 1.7912x; 1.3306x over previous
#include <cuda_runtime.h>
#include <cuda_fp16.h>

#define N_NODES 100000
#define N_EDGES 1600000
#define DIM 128
#define EDIM 16
#define NBLK 98             // ceil(100000/1024)

typedef unsigned long long u64;

// f32x2 packed math (sm_103a; ptxas never auto-fuses these)
#define FMA2(d, a, b, c) asm("fma.rn.f32x2 %0, %1, %2, %3;" : "=l"(d) : "l"(a), "l"(b), "l"(c))
#define ADD2(d, a, b)    asm("add.rn.f32x2 %0, %1, %2;"     : "=l"(d) : "l"(a), "l"(b))
#define PACK2(d, lo, hi) asm("mov.b64 %0, {%1, %2};" : "=l"(d) : "r"(__float_as_uint(lo)), "r"(__float_as_uint(hi)))
#define UNPK2(lo, hi, v) do { unsigned _ulo, _uhi; asm("mov.b64 {%0, %1}, %2;" : "=r"(_ulo), "=r"(_uhi) : "l"(v)); lo = __uint_as_float(_ulo); hi = __uint_as_float(_uhi); } while (0)

// ---------------- static scratch (no allocations allowed) ----------------
__device__ __align__(16) float    g_h[N_NODES * DIM];    // node features between layers
__device__ __align__(16) __half   g_glh[N_NODES * DIM];  // x @ Wl + bl (fp16, 25MB)
__device__ __align__(16) float    g_gr[N_NODES * DIM];   // x @ Wr + br
__device__ __align__(16) unsigned g_eacsr[(size_t)N_EDGES * EDIM]; // EA half2(v,v), CSR order
__device__ __align__(16) __half   g_ee[(size_t)N_EDGES * DIM];     // edge transform, CSR order
__device__ int   g_cnt[N_NODES];                      // zero at load; re-zeroed by scan1
__device__ int   g_off[N_NODES + 1];
__device__ int   g_cursor[N_NODES];
__device__ int   g_bsum[128];
__device__ int   g_srcarr[N_EDGES];                   // src node per CSR position
__device__ int   g_epos[N_EDGES];                     // edge -> CSR position
__device__ float g_stats[2 * DIM];                    // sum | sumsq (re-zeroed by bn_finalize)
__device__ float g_bnp[2 * DIM];                      // scale | shift

// ---------------- CSR build ----------------
// edge_index is INT32 (JAX x64-disabled downcast)
__global__ void k_hist(const int* __restrict__ ei, int* __restrict__ cnt) {
    int e = blockIdx.x * blockDim.x + threadIdx.x;
    if (e < N_EDGES) atomicAdd(&cnt[ei[N_EDGES + e]], 1);
}

__global__ void k_scan1(int* __restrict__ cnt, int* __restrict__ off,
                        int* __restrict__ bsum) {
    __shared__ int s[1024];
    int tid = threadIdx.x;
    int i = blockIdx.x * 1024 + tid;
    int v = (i < N_NODES) ? cnt[i] : 0;
    if (i < N_NODES) cnt[i] = 0;           // re-zero for next call
    s[tid] = v; __syncthreads();
    for (int d = 1; d < 1024; d <<= 1) {
        int t = (tid >= d) ? s[tid - d] : 0;
        __syncthreads();
        s[tid] += t;
        __syncthreads();
    }
    if (i < N_NODES) off[i] = s[tid] - v;   // exclusive within block
    if (tid == 1023) bsum[blockIdx.x] = s[1023];
}

__global__ void k_scan23(int* __restrict__ off, const int* __restrict__ bsum,
                         int* __restrict__ cursor) {
    __shared__ int sp[NBLK];
    int tid = threadIdx.x;
    if (tid == 0) {
        int acc = 0;
        for (int b = 0; b < NBLK; b++) { sp[b] = acc; acc += bsum[b]; }
    }
    __syncthreads();
    int i = blockIdx.x * blockDim.x + tid;
    if (i < N_NODES) {
        int o = off[i] + sp[i >> 10];
        off[i] = o;
        cursor[i] = o;
    }
    if (i == 0) off[N_NODES] = N_EDGES;
}

__global__ void k_scatter(const int* __restrict__ ei, int* __restrict__ cursor,
                          int* __restrict__ srcarr, int* __restrict__ epos) {
    int e = blockIdx.x * blockDim.x + threadIdx.x;
    if (e < N_EDGES) {
        int src = ei[e];
        int dst = ei[N_EDGES + e];
        int pos = atomicAdd(&cursor[dst], 1);
        srcarr[pos] = src;
        epos[e] = pos;
    }
}

// ---------------- one-time permute: EA (f32) -> half2(v,v) rows in CSR order -
// 64B-granule scatter write, 102MB total, amortized over 3 layers.
__global__ __launch_bounds__(256) void k_permute(
    const float* __restrict__ EA, const int* __restrict__ epos,
    unsigned* __restrict__ eacsr)
{
    int e = blockIdx.x * 256 + threadIdx.x;
    int pos = epos[e];
    const float4* src = (const float4*)(EA + (size_t)e * EDIM);
    uint4* dst = (uint4*)(eacsr + (size_t)pos * EDIM);
#pragma unroll
    for (int i = 0; i < 4; i++) {
        float4 v = src[i];
        __half2 h0 = __float2half2_rn(v.x);
        __half2 h1 = __float2half2_rn(v.y);
        __half2 h2 = __float2half2_rn(v.z);
        __half2 h3 = __float2half2_rn(v.w);
        uint4 o;
        o.x = *reinterpret_cast<unsigned*>(&h0);
        o.y = *reinterpret_cast<unsigned*>(&h1);
        o.z = *reinterpret_cast<unsigned*>(&h2);
        o.w = *reinterpret_cast<unsigned*>(&h3);
        dst[i] = o;
    }
}

// ---------------- dual node GEMM: glh = fp16(f(h)@Wl+bl), gr = f(h)@Wr+br ----
#define SXS 20
__global__ __launch_bounds__(128) void k_gemm_dual(
    const float* __restrict__ h, int applyBN, const float* __restrict__ bnp,
    const float* __restrict__ Wl, const float* __restrict__ bl,
    const float* __restrict__ Wr, const float* __restrict__ br,
    __half* __restrict__ glh, float* __restrict__ gr)
{
    __shared__ __align__(16) float sx[128 * SXS];
    __shared__ float sSc[DIM], sSh[DIM];
    int tid = threadIdx.x;
    sSc[tid] = bnp[tid];
    sSh[tid] = bnp[DIM + tid];
    __syncthreads();
    int n0 = blockIdx.x * 16;
    {
        int k = tid;
        float sc = sSc[k], sh = sSh[k];
#pragma unroll
        for (int it = 0; it < 16; it++) {
            float v = h[(size_t)(n0 + it) * DIM + k];
            if (applyBN) {
                v = v * sc + sh;
                v = v > 0.f ? v : 0.02f * v;
            }
            sx[k * SXS + it] = v;
        }
    }
    __syncthreads();
    int j = tid;
    u64 accl[8], accr[8];
    u64 zz; PACK2(zz, 0.f, 0.f);
#pragma unroll
    for (int p = 0; p < 8; p++) { accl[p] = zz; accr[p] = zz; }
#pragma unroll 4
    for (int k = 0; k < 128; k++) {
        float wl = Wl[k * DIM + j];
        float wr = Wr[k * DIM + j];
        u64 wl2, wr2;
        PACK2(wl2, wl, wl);
        PACK2(wr2, wr, wr);
        const ulonglong2* xp2 = (const ulonglong2*)(sx + k * SXS);
#pragma unroll
        for (int p = 0; p < 4; p++) {
            ulonglong2 xv = xp2[p];         // LDS.128
            FMA2(accl[2 * p],     xv.x, wl2, accl[2 * p]);
            FMA2(accr[2 * p],     xv.x, wr2, accr[2 * p]);
            FMA2(accl[2 * p + 1], xv.y, wl2, accl[2 * p + 1]);
            FMA2(accr[2 * p + 1], xv.y, wr2, accr[2 * p + 1]);
        }
    }
    float blv = bl[j], brv = br[j];
#pragma unroll
    for (int p = 0; p < 8; p++) {
        float l0, l1, r0, r1;
        UNPK2(l0, l1, accl[p]);
        UNPK2(r0, r1, accr[p]);
        size_t b0 = (size_t)(n0 + 2 * p) * DIM + j;
        glh[b0] = __float2half_rn(l0 + blv);        gr[b0] = r0 + brv;
        glh[b0 + DIM] = __float2half_rn(l1 + blv);  gr[b0 + DIM] = r1 + brv;
    }
}

// ---------------- final projection (f32x2) ----------------
__global__ __launch_bounds__(128) void k_gemm_final(
    const float* __restrict__ h, const float* __restrict__ bnp,
    const float* __restrict__ Wf, const float* __restrict__ bf,
    float* __restrict__ out)
{
    __shared__ __align__(16) float sx[128 * SXS];
    __shared__ float sSc[DIM], sSh[DIM];
    int tid = threadIdx.x;
    sSc[tid] = bnp[tid];
    sSh[tid] = bnp[DIM + tid];
    __syncthreads();
    int n0 = blockIdx.x * 16;
    {
        int k = tid;
        float sc = sSc[k], sh = sSh[k];
#pragma unroll
        for (int it = 0; it < 16; it++) {
            float v = h[(size_t)(n0 + it) * DIM + k];
            v = v * sc + sh;
            v = v > 0.f ? v : 0.02f * v;
            sx[k * SXS + it] = v;
        }
    }
    __syncthreads();
    int j = tid;
    u64 acc[8];
    u64 zz; PACK2(zz, 0.f, 0.f);
#pragma unroll
    for (int p = 0; p < 8; p++) acc[p] = zz;
#pragma unroll 4
    for (int k = 0; k < 128; k++) {
        float wf = Wf[k * DIM + j];
        u64 wf2; PACK2(wf2, wf, wf);
        const ulonglong2* xp2 = (const ulonglong2*)(sx + k * SXS);
#pragma unroll
        for (int p = 0; p < 4; p++) {
            ulonglong2 xv = xp2[p];
            FMA2(acc[2 * p],     xv.x, wf2, acc[2 * p]);
            FMA2(acc[2 * p + 1], xv.y, wf2, acc[2 * p + 1]);
        }
    }
    float bfv = bf[j];
#pragma unroll
    for (int p = 0; p < 8; p++) {
        float o0, o1;
        UNPK2(o0, o1, acc[p]);
        size_t b0 = (size_t)(n0 + 2 * p) * DIM + j;
        out[b0] = o0 + bfv;
        out[b0 + DIM] = o1 + bfv;
    }
}

// ---------------- edge transform GEMM (all-fp16, CSR-ordered I/O) ------------
// Identical compute to R13's measured-good kernel; input array is simply the
// CSR-permuted copy, so output lands in CSR order with sequential writes.
__global__ __launch_bounds__(256) void k_ee(
    const unsigned* __restrict__ eacsr, const float* __restrict__ We,
    __half* __restrict__ ee)
{
    __shared__ __align__(16) uint4 sbuf[256 * 4];   // 256 edges x 64B = 16KB
    int tid = threadIdx.x;
    int lane = tid & 31;
    int wrp = tid >> 5;
    int jb = lane * 4;

    __half2 we01h[16], we23h[16];
#pragma unroll
    for (int kk = 0; kk < 16; kk++) {
        float4 wv = *(const float4*)(We + kk * DIM + jb);
        we01h[kk] = __floats2half2_rn(wv.x, wv.y);
        we23h[kk] = __floats2half2_rn(wv.z, wv.w);
    }

    size_t ebase = (size_t)blockIdx.x * 256;
    const uint4* gp = (const uint4*)(eacsr + ebase * EDIM);
#pragma unroll
    for (int i = 0; i < 4; i++)
        sbuf[tid + i * 256] = gp[tid + i * 256];    // coalesced, MLP=4/thread
    __syncthreads();

    int le0 = wrp * 32;
#pragma unroll 2
    for (int q = 0; q < 32; q++) {
        int le = le0 + q;
        uint4 ua = sbuf[le * 4 + 0];                // LDS.128 broadcast
        uint4 ub = sbuf[le * 4 + 1];
        uint4 uc = sbuf[le * 4 + 2];
        uint4 ud = sbuf[le * 4 + 3];
        __half2 z = __float2half2_rn(0.f);
        __half2 a01 = z, b01 = z, a23 = z, b23 = z;
#define EE_STEP(u, k0)                                                        \
        {                                                                     \
            __half2 s0 = *reinterpret_cast<__half2*>(&(u).x);                 \
            __half2 s1 = *reinterpret_cast<__half2*>(&(u).y);                 \
            __half2 s2 = *reinterpret_cast<__half2*>(&(u).z);                 \
            __half2 s3 = *reinterpret_cast<__half2*>(&(u).w);                 \
            a01 = __hfma2(s0, we01h[(k0) + 0], a01);                          \
            a23 = __hfma2(s0, we23h[(k0) + 0], a23);                          \
            b01 = __hfma2(s1, we01h[(k0) + 1], b01);                          \
            b23 = __hfma2(s1, we23h[(k0) + 1], b23);                          \
            a01 = __hfma2(s2, we01h[(k0) + 2], a01);                          \
            a23 = __hfma2(s2, we23h[(k0) + 2], a23);                          \
            b01 = __hfma2(s3, we01h[(k0) + 3], b01);                          \
            b23 = __hfma2(s3, we23h[(k0) + 3], b23);                          \
        }
        EE_STEP(ua, 0)
        EE_STEP(ub, 4)
        EE_STEP(uc, 8)
        EE_STEP(ud, 12)
#undef EE_STEP
        __half2 r01 = __hadd2(a01, b01);
        __half2 r23 = __hadd2(a23, b23);
        uint2 o;
        o.x = *reinterpret_cast<unsigned*>(&r01);
        o.y = *reinterpret_cast<unsigned*>(&r23);
        *(uint2*)(ee + (ebase + le) * DIM + jb) = o;   // 256B coalesced per warp
    }
}

// ---------------- fused GATv2 aggregation: one warp per destination node -----
// ee read SEQUENTIALLY (CSR order -> streaming DRAM); srcarr sequential;
// only random access is glh[src] (25MB, L2-resident). R13 loop structure.
__global__ __launch_bounds__(256) void k_aggregate(
    const int* __restrict__ off, const int* __restrict__ srcarr,
    const __half* __restrict__ ee,
    const __half* __restrict__ glh, const float* __restrict__ gr,
    const float* __restrict__ att, const float* __restrict__ bias,
    float* __restrict__ hout, float* __restrict__ stats)
{
    __shared__ float sS[8 * DIM];
    __shared__ float sQ[8 * DIM];
    int tid = threadIdx.x;
    int lane = tid & 31;
    int wrp = tid >> 5;
    int n = blockIdx.x * 8 + wrp;
    int jb = lane * 4;

    float4 a4 = *(const float4*)(att + jb);
    float4 b4 = *(const float4*)(bias + jb);

    float o0 = 0.f, o1 = 0.f, o2 = 0.f, o3 = 0.f;
    if (n < N_NODES) {
        ulonglong2 grv = *(const ulonglong2*)(gr + (size_t)n * DIM + jb);
        u64 gr01 = grv.x, gr23 = grv.y;
        u64 acc01, acc23;
        PACK2(acc01, 0.f, 0.f);
        acc23 = acc01;
        float den = 0.f;
        int beg = off[n], end = off[n + 1];
#pragma unroll 2
        for (int p = beg; p < end; p++) {
            int s = srcarr[p];                                          // sequential
            uint2 ev = *(const uint2*)(ee + (size_t)p * DIM + jb);      // sequential
            uint2 gv = *(const uint2*)(glh + (size_t)s * DIM + jb);     // L2 gather
            __half2 ha = *reinterpret_cast<__half2*>(&ev.x);
            __half2 hb = *reinterpret_cast<__half2*>(&ev.y);
            __half2 ga = *reinterpret_cast<__half2*>(&gv.x);
            __half2 gb = *reinterpret_cast<__half2*>(&gv.y);
            float2 ef0 = __half22float2(ha);
            float2 ef1 = __half22float2(hb);
            float2 gf0 = __half22float2(ga);
            float2 gf1 = __half22float2(gb);
            u64 ee01, ee23, g01, g23;
            PACK2(ee01, ef0.x, ef0.y);
            PACK2(ee23, ef1.x, ef1.y);
            PACK2(g01, gf0.x, gf0.y);
            PACK2(g23, gf1.x, gf1.y);
            u64 e01, e23;
            ADD2(e01, g01, gr01);
            ADD2(e23, g23, gr23);
            ADD2(e01, e01, ee01);
            ADD2(e23, e23, ee23);
            float x0, x1, x2, x3;
            UNPK2(x0, x1, e01);
            UNPK2(x2, x3, e23);
            x0 = x0 > 0.f ? x0 : 0.2f * x0;     // GATv2 leaky relu 0.2
            x1 = x1 > 0.f ? x1 : 0.2f * x1;
            x2 = x2 > 0.f ? x2 : 0.2f * x2;
            x3 = x3 > 0.f ? x3 : 0.2f * x3;
            float t = x0 * a4.x;
            t = fmaf(x1, a4.y, t);
            t = fmaf(x2, a4.z, t);
            t = fmaf(x3, a4.w, t);
            t += __shfl_xor_sync(0xffffffffu, t, 1);
            t += __shfl_xor_sync(0xffffffffu, t, 2);
            t += __shfl_xor_sync(0xffffffffu, t, 4);
            float w = __expf(t);
            den += w;
            u64 ww; PACK2(ww, w, w);
            FMA2(acc01, ww, g01, acc01);
            FMA2(acc23, ww, g23, acc23);
        }
        float rden = 1.0f / (den + 1e-16f);
        float a0, a1, a2, a3;
        UNPK2(a0, a1, acc01);
        UNPK2(a2, a3, acc23);
        o0 = a0 * rden + b4.x;
        o1 = a1 * rden + b4.y;
        o2 = a2 * rden + b4.z;
        o3 = a3 * rden + b4.w;
        *(float4*)(hout + (size_t)n * DIM + jb) = make_float4(o0, o1, o2, o3);
    }
    // BN partials: per-warp disjoint smem slices, no smem atomics
    int base = wrp * DIM + jb;
    sS[base + 0] = o0;  sQ[base + 0] = o0 * o0;
    sS[base + 1] = o1;  sQ[base + 1] = o1 * o1;
    sS[base + 2] = o2;  sQ[base + 2] = o2 * o2;
    sS[base + 3] = o3;  sQ[base + 3] = o3 * o3;
    __syncthreads();
    if (tid < DIM) {
        float s = 0.f, q = 0.f;
#pragma unroll
        for (int w = 0; w < 8; w++) {
            s += sS[w * DIM + tid];
            q += sQ[w * DIM + tid];
        }
        atomicAdd(&stats[tid], s);
        atomicAdd(&stats[DIM + tid], q);
    }
}

// ---------------- BN stats finalize (and reset accumulators) ----------------
__global__ void k_bn_finalize(float* __restrict__ stats,
                              const float* __restrict__ gamma,
                              const float* __restrict__ beta,
                              float* __restrict__ bnp)
{
    int j = threadIdx.x;
    float inv_n = 1.0f / (float)N_NODES;
    float mu = stats[j] * inv_n;
    float var = stats[DIM + j] * inv_n - mu * mu;
    float rs = rsqrtf(var + 1e-5f);
    float sc = rs * gamma[j];
    bnp[j] = sc;
    bnp[DIM + j] = beta[j] - mu * sc;
    stats[j] = 0.f;
    stats[DIM + j] = 0.f;
}

// ---------------- launch ----------------
extern "C" void kernel_launch(void* const* d_in, const int* in_sizes, int n_in,
                              void* d_out, int out_size)
{
    const float* x    = (const float*)d_in[0];
    const int*   ei   = (const int*)d_in[1];     // int32
    const float* ea   = (const float*)d_in[2];
    const float* Wl   = (const float*)d_in[3];
    const float* bl   = (const float*)d_in[4];
    const float* Wr   = (const float*)d_in[5];
    const float* br   = (const float*)d_in[6];
    const float* We   = (const float*)d_in[7];
    const float* att  = (const float*)d_in[8];
    const float* bias = (const float*)d_in[9];
    const float* gamma= (const float*)d_in[10];
    const float* beta = (const float*)d_in[11];
    const float* Wf   = (const float*)d_in[12];
    const float* bf   = (const float*)d_in[13];
    float* out = (float*)d_out;

    float *p_h, *p_gr, *p_stats, *p_bnp;
    unsigned *p_eacsr;
    __half *p_ee, *p_glh;
    int *p_cnt, *p_off, *p_cur, *p_bsum, *p_src, *p_epos;
    cudaGetSymbolAddress((void**)&p_h,     g_h);
    cudaGetSymbolAddress((void**)&p_glh,   g_glh);
    cudaGetSymbolAddress((void**)&p_gr,    g_gr);
    cudaGetSymbolAddress((void**)&p_eacsr, g_eacsr);
    cudaGetSymbolAddress((void**)&p_ee,    g_ee);
    cudaGetSymbolAddress((void**)&p_stats, g_stats);
    cudaGetSymbolAddress((void**)&p_bnp,   g_bnp);
    cudaGetSymbolAddress((void**)&p_cnt,   g_cnt);
    cudaGetSymbolAddress((void**)&p_off,   g_off);
    cudaGetSymbolAddress((void**)&p_cur,   g_cursor);
    cudaGetSymbolAddress((void**)&p_bsum,  g_bsum);
    cudaGetSymbolAddress((void**)&p_src,   g_srcarr);
    cudaGetSymbolAddress((void**)&p_epos,  g_epos);

    int gemm_blocks = N_NODES / 16;            // 6250 (exact)
    int agg_blocks  = N_NODES / 8;             // 12500 (exact)
    int ee_blocks   = N_EDGES / 256;           // 6250

    // launch #4 = k_gemm_dual (ncu capture slot)
    k_hist<<<(N_EDGES + 255) / 256, 256>>>(ei, p_cnt);                   // 1
    k_scan1<<<NBLK, 1024>>>(p_cnt, p_off, p_bsum);                       // 2
    k_scan23<<<(N_NODES + 255) / 256, 256>>>(p_off, p_bsum, p_cur);      // 3
    k_gemm_dual<<<gemm_blocks, 128>>>(x, 0, p_bnp, Wl, bl, Wr, br,
                                      p_glh, p_gr);                      // 4 (profiled)
    k_scatter<<<(N_EDGES + 255) / 256, 256>>>(ei, p_cur, p_src, p_epos); // 5
    k_permute<<<N_EDGES / 256, 256>>>(ea, p_epos, p_eacsr);              // 6 (once)

    for (int L = 0; L < 3; L++) {
        if (L > 0) {
            k_gemm_dual<<<gemm_blocks, 128>>>(p_h, 1, p_bnp,
                                              Wl + L * DIM * DIM, bl + L * DIM,
                                              Wr + L * DIM * DIM, br + L * DIM,
                                              p_glh, p_gr);
        }
        k_ee<<<ee_blocks, 256>>>(p_eacsr, We + L * EDIM * DIM, p_ee);
        k_aggregate<<<agg_blocks, 256>>>(p_off, p_src, p_ee, p_glh, p_gr,
                                         att + L * DIM, bias + L * DIM,
                                         p_h, p_stats);
        k_bn_finalize<<<1, 128>>>(p_stats, gamma + L * DIM, beta + L * DIM, p_bnp);
    }
    k_gemm_final<<<gemm_blocks, 128>>>(p_h, p_bnp, Wf, bf, out);
}